// round 12
// baseline (speedup 1.0000x reference)
#include <cuda_runtime.h>
#include <math.h>

// ---------------- static device scratch (no cudaMalloc allowed) -------------
#define MAXV    16384
#define MAXS    66
#define MAXPTS  (66*66*66)
#define TPB     256
#define VCHUNK  256               // verts per block (smem tile) == TPB
#define MAXGROUPS2 (17*33*65)     // worst case: GPP=17, PR=33, sz=65
#define WEPS    1e-6f

__device__ float  g_vn[MAXV*3];
__device__ float  g_dual[MAXV];
__device__ float4 g_vA[MAXV];     // x,y,z, na.x
__device__ float2 g_vB[MAXV];     // na.y, na.z
__device__ float  g_wsum[MAXPTS];
__device__ float  g_vol[MAXPTS];
__device__ float  g_axes[3][MAXS];
__device__ int    g_dims[4];      // sx, sy, sz, npts
__device__ int    g_b0[3];
__device__ int    g_bsz[3];
__device__ float  g_ratio[3];
__device__ int    g_faces64;      // 1 if faces buffer is int64, 0 if int32

__device__ __forceinline__ float fsqrt_ap(float x) {
    float r; asm("sqrt.approx.f32 %0, %1;" : "=f"(r) : "f"(x)); return r;
}
__device__ __forceinline__ float frcp_ap(float x) {
    float r; asm("rcp.approx.f32 %0, %1;" : "=f"(r) : "f"(x)); return r;
}

// ---------------- K_setup: zero vn/dual + detect dtype + bbox + layout ------
__global__ void k_setup(const float* __restrict__ verts, int V, int R,
                        const int* __restrict__ fdw, int n32) {
    __shared__ float s[6][256];
    int t = threadIdx.x;

    for (int i = t; i < MAXV*3; i += 256) g_vn[i] = 0.0f;
    for (int i = t; i < MAXV;   i += 256) g_dual[i] = 0.0f;

    if (t == 0) {
        int lim = n32 < 4096 ? n32 : 4096;
        int any = 0;
        for (int i = 1; i < lim; i += 2)
            if (fdw[i] != 0) { any = 1; break; }
        g_faces64 = any ? 0 : 1;   // int64 LE small indices -> odd dwords zero
    }

    float mn0 = 1e30f, mn1 = 1e30f, mn2 = 1e30f;
    float mx0 = -1e30f, mx1 = -1e30f, mx2 = -1e30f;
    for (int v = t; v < V; v += 256) {
        float x = verts[3*v+0], y = verts[3*v+1], z = verts[3*v+2];
        mn0 = fminf(mn0, x); mx0 = fmaxf(mx0, x);
        mn1 = fminf(mn1, y); mx1 = fmaxf(mx1, y);
        mn2 = fminf(mn2, z); mx2 = fmaxf(mx2, z);
    }
    s[0][t] = mn0; s[1][t] = mn1; s[2][t] = mn2;
    s[3][t] = mx0; s[4][t] = mx1; s[5][t] = mx2;
    __syncthreads();
    for (int off = 128; off > 0; off >>= 1) {
        if (t < off) {
            s[0][t] = fminf(s[0][t], s[0][t+off]);
            s[1][t] = fminf(s[1][t], s[1][t+off]);
            s[2][t] = fminf(s[2][t], s[2][t+off]);
            s[3][t] = fmaxf(s[3][t], s[3][t+off]);
            s[4][t] = fmaxf(s[4][t], s[4][t+off]);
            s[5][t] = fmaxf(s[5][t], s[5][t+off]);
        }
        __syncthreads();
    }
    if (t == 0) {
        float bmin[3] = { s[0][0], s[1][0], s[2][0] };
        float bmax[3] = { s[3][0], s[4][0], s[5][0] };
        float blen[3], mb = 0.0f;
        for (int i = 0; i < 3; i++) { blen[i] = __fadd_rn(bmax[i], -bmin[i]); mb = fmaxf(mb, blen[i]); }
        float steplen = __fdiv_rn(mb, 64.0f);     // BBOX_DENSITY = 64
        int step[3];
        for (int i = 0; i < 3; i++) {
            int st = (int)__fdiv_rn(blen[i], steplen) + 1;
            if (st < 1) st = 1;
            if (st > 65) st = 65;
            step[i] = st;
        }
        g_dims[0] = step[0]; g_dims[1] = step[1]; g_dims[2] = step[2];
        g_dims[3] = step[0] * step[1] * step[2];
        float Rf = (float)R;
        for (int i = 0; i < 3; i++) {
            int n = step[i];
            double a = (double)bmin[i], b = (double)bmax[i];
            if (n > 1) {
                double stp = (b - a) / (double)(n - 1);
                for (int j = 0; j < n; j++) g_axes[i][j] = (float)((double)j * stp + a);
                g_axes[i][n-1] = (float)b;
            } else {
                g_axes[i][0] = (float)a;
            }
            float lo = floorf(__fmul_rn(__fmul_rn(__fadd_rn(bmin[i], 1.0f), Rf), 0.5f));
            float hi = floorf(__fmul_rn(__fmul_rn(__fadd_rn(bmax[i], 1.0f), Rf), 0.5f));
            int b0 = (int)lo, b1 = (int)hi;
            g_b0[i] = b0;
            int bs = b1 - b0 + 1;
            if (bs < 1) bs = 1;
            g_bsz[i] = bs;
            g_ratio[i] = (float)((double)n / (double)bs);
        }
    }
}

// ---------------- K2: per-face cross + angle-weighted area scatter ----------
__global__ void k_faces(const float* __restrict__ verts,
                        const void* __restrict__ faces_raw, int F, int V) {
    int f = blockIdx.x * blockDim.x + threadIdx.x;
    if (f >= F) return;
    int i0, i1, i2;
    if (g_faces64) {
        const long long* ff = (const long long*)faces_raw;
        i0 = (int)ff[3*f+0]; i1 = (int)ff[3*f+1]; i2 = (int)ff[3*f+2];
    } else {
        const int* fi = (const int*)faces_raw;
        i0 = fi[3*f+0]; i1 = fi[3*f+1]; i2 = fi[3*f+2];
    }
    i0 = min(max(i0, 0), V-1); i1 = min(max(i1, 0), V-1); i2 = min(max(i2, 0), V-1);

    float v0x = verts[3*i0+0], v0y = verts[3*i0+1], v0z = verts[3*i0+2];
    float v1x = verts[3*i1+0], v1y = verts[3*i1+1], v1z = verts[3*i1+2];
    float v2x = verts[3*i2+0], v2y = verts[3*i2+1], v2z = verts[3*i2+2];

    float Ax = v1x - v0x, Ay = v1y - v0y, Az = v1z - v0z;
    float Bx = v2x - v1x, By = v2y - v1y, Bz = v2z - v1z;
    float Cx = v0x - v2x, Cy = v0y - v2y, Cz = v0z - v2z;
    float ex = v2x - v0x, ey = v2y - v0y, ez = v2z - v0z;

    float crx = Ay*ez - Az*ey;
    float cry = Az*ex - Ax*ez;
    float crz = Ax*ey - Ay*ex;
    float area = 0.5f * sqrtf(crx*crx + cry*cry + crz*crz);

    float nA = sqrtf(Ax*Ax + Ay*Ay + Az*Az);
    float nB = sqrtf(Bx*Bx + By*By + Bz*Bz);
    float nC = sqrtf(Cx*Cx + Cy*Cy + Cz*Cz);

    float d_ac = Ax*Cx + Ay*Cy + Az*Cz;
    float d_ab = Ax*Bx + Ay*By + Az*Bz;
    float d_bc = Bx*Cx + By*Cy + Bz*Cz;

    float a0 = acosf(fminf(fmaxf(-d_ac / (1e-10f + nA*nC), -1.0f), 1.0f));
    float a1 = acosf(fminf(fmaxf(-d_ab / (1e-10f + nA*nB), -1.0f), 1.0f));
    float a2 = acosf(fminf(fmaxf(-d_bc / (1e-10f + nB*nC), -1.0f), 1.0f));

    float s0 = sinf(2.0f*a0), s1 = sinf(2.0f*a1), s2 = sinf(2.0f*a2);
    float ssum = s0 + s1 + s2 + 1e-8f;
    float w0 = s0 / ssum, w1 = s1 / ssum, w2 = s2 / ssum;
    float wp0 = 0.5f * (w2 + w1);
    float wp1 = 0.5f * (w0 + w2);
    float wp2 = 0.5f * (w1 + w0);

    atomicAdd(&g_vn[3*i0+0], crx); atomicAdd(&g_vn[3*i0+1], cry); atomicAdd(&g_vn[3*i0+2], crz);
    atomicAdd(&g_vn[3*i1+0], crx); atomicAdd(&g_vn[3*i1+1], cry); atomicAdd(&g_vn[3*i1+2], crz);
    atomicAdd(&g_vn[3*i2+0], crx); atomicAdd(&g_vn[3*i2+1], cry); atomicAdd(&g_vn[3*i2+2], crz);
    atomicAdd(&g_dual[i0], wp0 * area);
    atomicAdd(&g_dual[i1], wp1 * area);
    atomicAdd(&g_dual[i2], wp2 * area);
}

// ---------------- K3: normalize normals, pack; also zero g_wsum --------------
__global__ void k_pack(const float* __restrict__ verts, int V, int Vpad) {
    int v = blockIdx.x * blockDim.x + threadIdx.x;
    int nthr = gridDim.x * blockDim.x;
    for (int i = v; i < MAXPTS; i += nthr) g_wsum[i] = 0.0f;
    if (v >= Vpad) return;
    if (v < V) {
        float nx = g_vn[3*v+0], ny = g_vn[3*v+1], nz = g_vn[3*v+2];
        float len = sqrtf(nx*nx + ny*ny + nz*nz);
        float il = 1.0f / fmaxf(len, 1e-12f);
        float d = g_dual[v];
        float sc = il * d;
        g_vA[v] = make_float4(verts[3*v+0], verts[3*v+1], verts[3*v+2], nx * sc);
        g_vB[v] = make_float2(ny * sc, nz * sc);
    } else {
        g_vA[v] = make_float4(0.f, 0.f, 0.f, 0.f);   // zero normal -> zero term
        g_vB[v] = make_float2(0.f, 0.f);
    }
}

// ---------------- K4: winding-number partial sums ----------------------------
// 4x x 2y tile per thread, axis-factorized shared work, and PAIRWISE batched
// reciprocals: rcp(dd_i*dd_j) + 2 muls recovers both inverses. vs Montgomery-4
// this removes 6 FMULs/vertex (the bound pipe) for +2 MUFU rcp (idle pipe).
// 57 float ops / 8 points = 7.125/pt.
__global__ void __launch_bounds__(TPB, 3) k_wind() {
    __shared__ float4 sV[VCHUNK];   // x,y,z,nx
    __shared__ float2 sW[VCHUNK];   // ny,nz
    const int sx = g_dims[0], sy = g_dims[1], sz = g_dims[2];
    const int GPP = (sx + 3) >> 2;          // 4-point groups per x-row
    const int PR  = (sy + 1) >> 1;          // y-row pairs
    const int ngroups = GPP * PR * sz;
    const int G0 = blockIdx.x * TPB;
    if (G0 >= ngroups) return;

    {
        int v  = threadIdx.x;              // VCHUNK == TPB
        int gv = blockIdx.y * VCHUNK + v;
        sV[v] = g_vA[gv];
        sW[v] = g_vB[gv];
    }
    __syncthreads();

    const int G = G0 + threadIdx.x;
    const bool gvalid = (G < ngroups);
    const int Gc = gvalid ? G : 0;
    const int gi = Gc % GPP;
    const int rr = Gc / GPP;
    const int jp = rr % PR;                 // y-pair index
    const int kz = rr / PR;
    const int ix0 = gi * 4;
    const int jy0 = jp * 2;
    const bool has1 = (jy0 + 1 < sy);
    const int jy1 = has1 ? (jy0 + 1) : jy0;
    int nval = sx - ix0; nval = nval > 4 ? 4 : nval;    // 1..4 valid x points
    const float px0 = g_axes[0][ix0];
    const float px1 = g_axes[0][min(ix0+1, sx-1)];
    const float px2 = g_axes[0][min(ix0+2, sx-1)];
    const float px3 = g_axes[0][min(ix0+3, sx-1)];
    const float py0 = g_axes[1][jy0];
    const float py1 = g_axes[1][jy1];
    const float pz  = g_axes[2][kz];
    float aA0=0.f, aA1=0.f, aA2=0.f, aA3=0.f;   // row jy0
    float aB0=0.f, aB1=0.f, aB2=0.f, aB3=0.f;   // row jy1

    #pragma unroll 2
    for (int v = 0; v < VCHUNK; v++) {
        float4 A  = sV[v];
        float2 Bv = sW[v];
        // z-shared (3 ops)
        float dz  = A.z - pz;
        float dzz = dz * dz;
        float tz  = dz * Bv.y;
        // x-shared (4 ops)
        float dx0 = A.x - px0, dx1 = A.x - px1, dx2 = A.x - px2, dx3 = A.x - px3;
        // ---- row A (jy0) ----
        {
            float dy  = A.y - py0;
            float ryz = fmaf(dy, dy, dzz);
            float tyz = fmaf(dy, Bv.x, tz);
            float r20 = fmaf(dx0, dx0, ryz);
            float r21 = fmaf(dx1, dx1, ryz);
            float r22 = fmaf(dx2, dx2, ryz);
            float r23 = fmaf(dx3, dx3, ryz);
            float dt0 = fmaf(dx0, A.w, tyz);
            float dt1 = fmaf(dx1, A.w, tyz);
            float dt2 = fmaf(dx2, A.w, tyz);
            float dt3 = fmaf(dx3, A.w, tyz);
            float dd0 = fmaf(r20, fsqrt_ap(r20), WEPS);
            float dd1 = fmaf(r21, fsqrt_ap(r21), WEPS);
            float dd2 = fmaf(r22, fsqrt_ap(r22), WEPS);
            float dd3 = fmaf(r23, fsqrt_ap(r23), WEPS);
            float Q01 = frcp_ap(dd0 * dd1);
            float Q23 = frcp_ap(dd2 * dd3);
            aA0 = fmaf(dt0, Q01 * dd1, aA0);
            aA1 = fmaf(dt1, Q01 * dd0, aA1);
            aA2 = fmaf(dt2, Q23 * dd3, aA2);
            aA3 = fmaf(dt3, Q23 * dd2, aA3);
        }
        // ---- row B (jy1) ----
        {
            float dy  = A.y - py1;
            float ryz = fmaf(dy, dy, dzz);
            float tyz = fmaf(dy, Bv.x, tz);
            float r20 = fmaf(dx0, dx0, ryz);
            float r21 = fmaf(dx1, dx1, ryz);
            float r22 = fmaf(dx2, dx2, ryz);
            float r23 = fmaf(dx3, dx3, ryz);
            float dt0 = fmaf(dx0, A.w, tyz);
            float dt1 = fmaf(dx1, A.w, tyz);
            float dt2 = fmaf(dx2, A.w, tyz);
            float dt3 = fmaf(dx3, A.w, tyz);
            float dd0 = fmaf(r20, fsqrt_ap(r20), WEPS);
            float dd1 = fmaf(r21, fsqrt_ap(r21), WEPS);
            float dd2 = fmaf(r22, fsqrt_ap(r22), WEPS);
            float dd3 = fmaf(r23, fsqrt_ap(r23), WEPS);
            float Q01 = frcp_ap(dd0 * dd1);
            float Q23 = frcp_ap(dd2 * dd3);
            aB0 = fmaf(dt0, Q01 * dd1, aB0);
            aB1 = fmaf(dt1, Q01 * dd0, aB1);
            aB2 = fmaf(dt2, Q23 * dd3, aB2);
            aB3 = fmaf(dt3, Q23 * dd2, aB3);
        }
    }

    if (gvalid) {
        int baseA = (kz * sy + jy0) * sx + ix0;
        atomicAdd(&g_wsum[baseA], aA0);
        if (nval > 1) atomicAdd(&g_wsum[baseA+1], aA1);
        if (nval > 2) atomicAdd(&g_wsum[baseA+2], aA2);
        if (nval > 3) atomicAdd(&g_wsum[baseA+3], aA3);
        if (has1) {
            int baseB = baseA + sx;
            atomicAdd(&g_wsum[baseB], aB0);
            if (nval > 1) atomicAdd(&g_wsum[baseB+1], aB1);
            if (nval > 2) atomicAdd(&g_wsum[baseB+2], aB2);
            if (nval > 3) atomicAdd(&g_wsum[baseB+3], aB3);
        }
    }
}

// ---------------- K4b: sigmoid ---------------------------------------------
__global__ void k_sig() {
    int i = blockIdx.x * blockDim.x + threadIdx.x;
    if (i >= g_dims[3]) return;
    float w = g_wsum[i] / 12.566370614359172f;     // / (4*pi)
    float x = (w - 0.5f) * 100.0f;
    g_vol[i] = 1.0f / (1.0f + __expf(-x));
}

// ---------------- K5: trilerp + scatter into R^3, transposed ----------------
__global__ void k_out(float* __restrict__ out, int R, int total) {
    int n = blockIdx.x * blockDim.x + threadIdx.x;
    if (n >= total) return;
    int k = n % R;
    int t = n / R;
    int j = t % R;
    int i = t / R;
    int a = k, b = j, c = i;              // whole axes (x, y, z)
    float val = 0.0f;
    int bi = a - g_b0[0], bj = b - g_b0[1], bk = c - g_b0[2];
    int bsx = g_bsz[0], bsy = g_bsz[1], bsz_ = g_bsz[2];
    if (bi >= 0 && bi < bsx && bj >= 0 && bj < bsy && bk >= 0 && bk < bsz_) {
        int sx = g_dims[0], sy = g_dims[1], sz = g_dims[2];
        float c0 = ((float)bi + 0.5f) * g_ratio[0] - 0.5f;
        float c1 = ((float)bj + 0.5f) * g_ratio[1] - 0.5f;
        float c2 = ((float)bk + 0.5f) * g_ratio[2] - 0.5f;
        c0 = fminf(fmaxf(c0, 0.0f), (float)(sx - 1));
        c1 = fminf(fmaxf(c1, 0.0f), (float)(sy - 1));
        c2 = fminf(fmaxf(c2, 0.0f), (float)(sz - 1));
        int i0 = (int)c0, j0 = (int)c1, k0 = (int)c2;
        float t0 = c0 - (float)i0, t1 = c1 - (float)j0, t2 = c2 - (float)k0;
        int i1 = min(i0 + 1, sx - 1);
        int j1 = min(j0 + 1, sy - 1);
        int k1 = min(k0 + 1, sz - 1);
        #define VOL(I,J,K) g_vol[((K)*sy + (J))*sx + (I)]
        float v000 = VOL(i0, j0, k0), v100 = VOL(i1, j0, k0);
        float v010 = VOL(i0, j1, k0), v110 = VOL(i1, j1, k0);
        float v001 = VOL(i0, j0, k1), v101 = VOL(i1, j0, k1);
        float v011 = VOL(i0, j1, k1), v111 = VOL(i1, j1, k1);
        #undef VOL
        float x00 = v000 + t0 * (v100 - v000);
        float x10 = v010 + t0 * (v110 - v010);
        float x01 = v001 + t0 * (v101 - v001);
        float x11 = v011 + t0 * (v111 - v011);
        float y0 = x00 + t1 * (x10 - x00);
        float y1 = x01 + t1 * (x11 - x01);
        val = y0 + t2 * (y1 - y0);
    }
    out[n] = val;
}

// ---------------- launcher ---------------------------------------------------
extern "C" void kernel_launch(void* const* d_in, const int* in_sizes, int n_in,
                              void* d_out, int out_size) {
    const float* verts = (const float*)d_in[0];
    const void*  faces = (const void*)d_in[1];
    int V = in_sizes[0] / 3;
    int F = in_sizes[1] / 3;
    if (V > MAXV) V = MAXV;
    int Vpad = ((V + VCHUNK - 1) / VCHUNK) * VCHUNK;
    if (Vpad > MAXV) Vpad = MAXV;

    double cr = cbrt((double)out_size);
    int R = (int)(cr + 0.5);

    k_setup<<<1, 256>>>(verts, V, R, (const int*)faces, in_sizes[1] * 2);
    k_faces<<<(F + 255) / 256, 256>>>(verts, faces, F, V);
    k_pack<<<Vpad / 256, 256>>>(verts, V, Vpad);

    dim3 gw((MAXGROUPS2 + TPB - 1) / TPB, Vpad / VCHUNK);
    k_wind<<<gw, TPB>>>();          // launch slot 3 (profiled)

    k_sig<<<(MAXPTS + 255) / 256, 256>>>();
    k_out<<<(out_size + 255) / 256, 256>>>((float*)d_out, R, out_size);
}

// round 13
// speedup vs baseline: 1.0757x; 1.0757x over previous
#include <cuda_runtime.h>
#include <math.h>

// ---------------- static device scratch (no cudaMalloc allowed) -------------
#define MAXV    16384
#define MAXS    66
#define MAXPTS  (66*66*66)
#define TPB     256
#define VCHUNK  256               // verts per block (smem tile) == TPB
#define MAXGROUPS4 (17*17*65)     // worst case: GPP=17, QR=17, sz=65
#define WEPS    1e-6f

__device__ float  g_vn[MAXV*3];
__device__ float  g_dual[MAXV];
__device__ float4 g_vA[MAXV];     // x,y,z, na.x
__device__ float2 g_vB[MAXV];     // na.y, na.z
__device__ float  g_wsum[MAXPTS];
__device__ float  g_vol[MAXPTS];
__device__ float  g_axes[3][MAXS];
__device__ int    g_dims[4];      // sx, sy, sz, npts
__device__ int    g_b0[3];
__device__ int    g_bsz[3];
__device__ float  g_ratio[3];
__device__ int    g_faces64;      // 1 if faces buffer is int64, 0 if int32

__device__ __forceinline__ float fsqrt_ap(float x) {
    float r; asm("sqrt.approx.f32 %0, %1;" : "=f"(r) : "f"(x)); return r;
}
__device__ __forceinline__ float frcp_ap(float x) {
    float r; asm("rcp.approx.f32 %0, %1;" : "=f"(r) : "f"(x)); return r;
}

// ---------------- K_setup: zero vn/dual + detect dtype + bbox + layout ------
__global__ void k_setup(const float* __restrict__ verts, int V, int R,
                        const int* __restrict__ fdw, int n32) {
    __shared__ float s[6][256];
    int t = threadIdx.x;

    for (int i = t; i < MAXV*3; i += 256) g_vn[i] = 0.0f;
    for (int i = t; i < MAXV;   i += 256) g_dual[i] = 0.0f;

    if (t == 0) {
        int lim = n32 < 4096 ? n32 : 4096;
        int any = 0;
        for (int i = 1; i < lim; i += 2)
            if (fdw[i] != 0) { any = 1; break; }
        g_faces64 = any ? 0 : 1;   // int64 LE small indices -> odd dwords zero
    }

    float mn0 = 1e30f, mn1 = 1e30f, mn2 = 1e30f;
    float mx0 = -1e30f, mx1 = -1e30f, mx2 = -1e30f;
    for (int v = t; v < V; v += 256) {
        float x = verts[3*v+0], y = verts[3*v+1], z = verts[3*v+2];
        mn0 = fminf(mn0, x); mx0 = fmaxf(mx0, x);
        mn1 = fminf(mn1, y); mx1 = fmaxf(mx1, y);
        mn2 = fminf(mn2, z); mx2 = fmaxf(mx2, z);
    }
    s[0][t] = mn0; s[1][t] = mn1; s[2][t] = mn2;
    s[3][t] = mx0; s[4][t] = mx1; s[5][t] = mx2;
    __syncthreads();
    for (int off = 128; off > 0; off >>= 1) {
        if (t < off) {
            s[0][t] = fminf(s[0][t], s[0][t+off]);
            s[1][t] = fminf(s[1][t], s[1][t+off]);
            s[2][t] = fminf(s[2][t], s[2][t+off]);
            s[3][t] = fmaxf(s[3][t], s[3][t+off]);
            s[4][t] = fmaxf(s[4][t], s[4][t+off]);
            s[5][t] = fmaxf(s[5][t], s[5][t+off]);
        }
        __syncthreads();
    }
    if (t == 0) {
        float bmin[3] = { s[0][0], s[1][0], s[2][0] };
        float bmax[3] = { s[3][0], s[4][0], s[5][0] };
        float blen[3], mb = 0.0f;
        for (int i = 0; i < 3; i++) { blen[i] = __fadd_rn(bmax[i], -bmin[i]); mb = fmaxf(mb, blen[i]); }
        float steplen = __fdiv_rn(mb, 64.0f);     // BBOX_DENSITY = 64
        int step[3];
        for (int i = 0; i < 3; i++) {
            int st = (int)__fdiv_rn(blen[i], steplen) + 1;
            if (st < 1) st = 1;
            if (st > 65) st = 65;
            step[i] = st;
        }
        g_dims[0] = step[0]; g_dims[1] = step[1]; g_dims[2] = step[2];
        g_dims[3] = step[0] * step[1] * step[2];
        float Rf = (float)R;
        for (int i = 0; i < 3; i++) {
            int n = step[i];
            double a = (double)bmin[i], b = (double)bmax[i];
            if (n > 1) {
                double stp = (b - a) / (double)(n - 1);
                for (int j = 0; j < n; j++) g_axes[i][j] = (float)((double)j * stp + a);
                g_axes[i][n-1] = (float)b;
            } else {
                g_axes[i][0] = (float)a;
            }
            float lo = floorf(__fmul_rn(__fmul_rn(__fadd_rn(bmin[i], 1.0f), Rf), 0.5f));
            float hi = floorf(__fmul_rn(__fmul_rn(__fadd_rn(bmax[i], 1.0f), Rf), 0.5f));
            int b0 = (int)lo, b1 = (int)hi;
            g_b0[i] = b0;
            int bs = b1 - b0 + 1;
            if (bs < 1) bs = 1;
            g_bsz[i] = bs;
            g_ratio[i] = (float)((double)n / (double)bs);
        }
    }
}

// ---------------- K2: per-face cross + angle-weighted area scatter ----------
__global__ void k_faces(const float* __restrict__ verts,
                        const void* __restrict__ faces_raw, int F, int V) {
    int f = blockIdx.x * blockDim.x + threadIdx.x;
    if (f >= F) return;
    int i0, i1, i2;
    if (g_faces64) {
        const long long* ff = (const long long*)faces_raw;
        i0 = (int)ff[3*f+0]; i1 = (int)ff[3*f+1]; i2 = (int)ff[3*f+2];
    } else {
        const int* fi = (const int*)faces_raw;
        i0 = fi[3*f+0]; i1 = fi[3*f+1]; i2 = fi[3*f+2];
    }
    i0 = min(max(i0, 0), V-1); i1 = min(max(i1, 0), V-1); i2 = min(max(i2, 0), V-1);

    float v0x = verts[3*i0+0], v0y = verts[3*i0+1], v0z = verts[3*i0+2];
    float v1x = verts[3*i1+0], v1y = verts[3*i1+1], v1z = verts[3*i1+2];
    float v2x = verts[3*i2+0], v2y = verts[3*i2+1], v2z = verts[3*i2+2];

    float Ax = v1x - v0x, Ay = v1y - v0y, Az = v1z - v0z;
    float Bx = v2x - v1x, By = v2y - v1y, Bz = v2z - v1z;
    float Cx = v0x - v2x, Cy = v0y - v2y, Cz = v0z - v2z;
    float ex = v2x - v0x, ey = v2y - v0y, ez = v2z - v0z;

    float crx = Ay*ez - Az*ey;
    float cry = Az*ex - Ax*ez;
    float crz = Ax*ey - Ay*ex;
    float area = 0.5f * sqrtf(crx*crx + cry*cry + crz*crz);

    float nA = sqrtf(Ax*Ax + Ay*Ay + Az*Az);
    float nB = sqrtf(Bx*Bx + By*By + Bz*Bz);
    float nC = sqrtf(Cx*Cx + Cy*Cy + Cz*Cz);

    float d_ac = Ax*Cx + Ay*Cy + Az*Cz;
    float d_ab = Ax*Bx + Ay*By + Az*Bz;
    float d_bc = Bx*Cx + By*Cy + Bz*Cz;

    float a0 = acosf(fminf(fmaxf(-d_ac / (1e-10f + nA*nC), -1.0f), 1.0f));
    float a1 = acosf(fminf(fmaxf(-d_ab / (1e-10f + nA*nB), -1.0f), 1.0f));
    float a2 = acosf(fminf(fmaxf(-d_bc / (1e-10f + nB*nC), -1.0f), 1.0f));

    float s0 = sinf(2.0f*a0), s1 = sinf(2.0f*a1), s2 = sinf(2.0f*a2);
    float ssum = s0 + s1 + s2 + 1e-8f;
    float w0 = s0 / ssum, w1 = s1 / ssum, w2 = s2 / ssum;
    float wp0 = 0.5f * (w2 + w1);
    float wp1 = 0.5f * (w0 + w2);
    float wp2 = 0.5f * (w1 + w0);

    atomicAdd(&g_vn[3*i0+0], crx); atomicAdd(&g_vn[3*i0+1], cry); atomicAdd(&g_vn[3*i0+2], crz);
    atomicAdd(&g_vn[3*i1+0], crx); atomicAdd(&g_vn[3*i1+1], cry); atomicAdd(&g_vn[3*i1+2], crz);
    atomicAdd(&g_vn[3*i2+0], crx); atomicAdd(&g_vn[3*i2+1], cry); atomicAdd(&g_vn[3*i2+2], crz);
    atomicAdd(&g_dual[i0], wp0 * area);
    atomicAdd(&g_dual[i1], wp1 * area);
    atomicAdd(&g_dual[i2], wp2 * area);
}

// ---------------- K3: normalize normals, pack; also zero g_wsum --------------
__global__ void k_pack(const float* __restrict__ verts, int V, int Vpad) {
    int v = blockIdx.x * blockDim.x + threadIdx.x;
    int nthr = gridDim.x * blockDim.x;
    for (int i = v; i < MAXPTS; i += nthr) g_wsum[i] = 0.0f;
    if (v >= Vpad) return;
    if (v < V) {
        float nx = g_vn[3*v+0], ny = g_vn[3*v+1], nz = g_vn[3*v+2];
        float len = sqrtf(nx*nx + ny*ny + nz*nz);
        float il = 1.0f / fmaxf(len, 1e-12f);
        float d = g_dual[v];
        float sc = il * d;
        g_vA[v] = make_float4(verts[3*v+0], verts[3*v+1], verts[3*v+2], nx * sc);
        g_vB[v] = make_float2(ny * sc, nz * sc);
    } else {
        g_vA[v] = make_float4(0.f, 0.f, 0.f, 0.f);   // zero normal -> zero term
        g_vB[v] = make_float2(0.f, 0.f);
    }
}

// ---------------- K4: winding-number partial sums ----------------------------
// 4x x 4y point tile per thread (R11 math, wider tile). Axis-factorized shared
// work + Montgomery-4 batch reciprocal per row (R12 showed pairwise regresses).
// 119 float ops / 16 points = 7.44/pt; LDS + loop overhead per point halved.
__global__ void __launch_bounds__(TPB, 3) k_wind() {
    __shared__ float4 sV[VCHUNK];   // x,y,z,nx
    __shared__ float2 sW[VCHUNK];   // ny,nz
    const int sx = g_dims[0], sy = g_dims[1], sz = g_dims[2];
    const int GPP = (sx + 3) >> 2;          // 4-point groups per x-row
    const int QR  = (sy + 3) >> 2;          // y quad-rows
    const int ngroups = GPP * QR * sz;
    const int G0 = blockIdx.x * TPB;
    if (G0 >= ngroups) return;

    {
        int v  = threadIdx.x;              // VCHUNK == TPB
        int gv = blockIdx.y * VCHUNK + v;
        sV[v] = g_vA[gv];
        sW[v] = g_vB[gv];
    }
    __syncthreads();

    const int G = G0 + threadIdx.x;
    const bool gvalid = (G < ngroups);
    const int Gc = gvalid ? G : 0;
    const int gi = Gc % GPP;
    const int rr = Gc / GPP;
    const int jq = rr % QR;                 // y quad index
    const int kz = rr / QR;
    const int ix0 = gi * 4;
    const int jy0 = jq * 4;
    int nvx = sx - ix0; nvx = nvx > 4 ? 4 : nvx;
    int nvy = sy - jy0; nvy = nvy > 4 ? 4 : nvy;
    const float px0 = g_axes[0][ix0];
    const float px1 = g_axes[0][min(ix0+1, sx-1)];
    const float px2 = g_axes[0][min(ix0+2, sx-1)];
    const float px3 = g_axes[0][min(ix0+3, sx-1)];
    float pys[4];
    #pragma unroll
    for (int r = 0; r < 4; r++) pys[r] = g_axes[1][min(jy0 + r, sy-1)];
    const float pz = g_axes[2][kz];
    float acc[4][4];
    #pragma unroll
    for (int r = 0; r < 4; r++)
        #pragma unroll
        for (int c = 0; c < 4; c++) acc[r][c] = 0.0f;

    for (int v = 0; v < VCHUNK; v++) {
        float4 A  = sV[v];
        float2 Bv = sW[v];
        // z-shared (3 ops)
        float dz  = A.z - pz;
        float dzz = dz * dz;
        float tz  = dz * Bv.y;
        // x-shared (4 ops)
        float dx0 = A.x - px0, dx1 = A.x - px1, dx2 = A.x - px2, dx3 = A.x - px3;
        #pragma unroll
        for (int r = 0; r < 4; r++) {
            float dy  = A.y - pys[r];
            float ryz = fmaf(dy, dy, dzz);
            float tyz = fmaf(dy, Bv.x, tz);
            float r20 = fmaf(dx0, dx0, ryz);
            float r21 = fmaf(dx1, dx1, ryz);
            float r22 = fmaf(dx2, dx2, ryz);
            float r23 = fmaf(dx3, dx3, ryz);
            float dt0 = fmaf(dx0, A.w, tyz);
            float dt1 = fmaf(dx1, A.w, tyz);
            float dt2 = fmaf(dx2, A.w, tyz);
            float dt3 = fmaf(dx3, A.w, tyz);
            float dd0 = fmaf(r20, fsqrt_ap(r20), WEPS);
            float dd1 = fmaf(r21, fsqrt_ap(r21), WEPS);
            float dd2 = fmaf(r22, fsqrt_ap(r22), WEPS);
            float dd3 = fmaf(r23, fsqrt_ap(r23), WEPS);
            float p2 = dd0 * dd1;
            float p3 = p2  * dd2;
            float p4 = p3  * dd3;
            float Q  = frcp_ap(p4);
            float Qa = Q  * dd3;
            float Qb = Qa * dd2;
            acc[r][3] = fmaf(dt3, Q  * p3,  acc[r][3]);
            acc[r][2] = fmaf(dt2, Qa * p2,  acc[r][2]);
            acc[r][1] = fmaf(dt1, Qb * dd0, acc[r][1]);
            acc[r][0] = fmaf(dt0, Qb * dd1, acc[r][0]);
        }
    }

    if (gvalid) {
        #pragma unroll
        for (int r = 0; r < 4; r++) {
            if (r < nvy) {
                int base = (kz * sy + (jy0 + r)) * sx + ix0;
                atomicAdd(&g_wsum[base], acc[r][0]);
                if (nvx > 1) atomicAdd(&g_wsum[base+1], acc[r][1]);
                if (nvx > 2) atomicAdd(&g_wsum[base+2], acc[r][2]);
                if (nvx > 3) atomicAdd(&g_wsum[base+3], acc[r][3]);
            }
        }
    }
}

// ---------------- K4b: sigmoid ---------------------------------------------
__global__ void k_sig() {
    int i = blockIdx.x * blockDim.x + threadIdx.x;
    if (i >= g_dims[3]) return;
    float w = g_wsum[i] / 12.566370614359172f;     // / (4*pi)
    float x = (w - 0.5f) * 100.0f;
    g_vol[i] = 1.0f / (1.0f + __expf(-x));
}

// ---------------- K5: trilerp + scatter into R^3, transposed ----------------
__global__ void k_out(float* __restrict__ out, int R, int total) {
    int n = blockIdx.x * blockDim.x + threadIdx.x;
    if (n >= total) return;
    int k = n % R;
    int t = n / R;
    int j = t % R;
    int i = t / R;
    int a = k, b = j, c = i;              // whole axes (x, y, z)
    float val = 0.0f;
    int bi = a - g_b0[0], bj = b - g_b0[1], bk = c - g_b0[2];
    int bsx = g_bsz[0], bsy = g_bsz[1], bsz_ = g_bsz[2];
    if (bi >= 0 && bi < bsx && bj >= 0 && bj < bsy && bk >= 0 && bk < bsz_) {
        int sx = g_dims[0], sy = g_dims[1], sz = g_dims[2];
        float c0 = ((float)bi + 0.5f) * g_ratio[0] - 0.5f;
        float c1 = ((float)bj + 0.5f) * g_ratio[1] - 0.5f;
        float c2 = ((float)bk + 0.5f) * g_ratio[2] - 0.5f;
        c0 = fminf(fmaxf(c0, 0.0f), (float)(sx - 1));
        c1 = fminf(fmaxf(c1, 0.0f), (float)(sy - 1));
        c2 = fminf(fmaxf(c2, 0.0f), (float)(sz - 1));
        int i0 = (int)c0, j0 = (int)c1, k0 = (int)c2;
        float t0 = c0 - (float)i0, t1 = c1 - (float)j0, t2 = c2 - (float)k0;
        int i1 = min(i0 + 1, sx - 1);
        int j1 = min(j0 + 1, sy - 1);
        int k1 = min(k0 + 1, sz - 1);
        #define VOL(I,J,K) g_vol[((K)*sy + (J))*sx + (I)]
        float v000 = VOL(i0, j0, k0), v100 = VOL(i1, j0, k0);
        float v010 = VOL(i0, j1, k0), v110 = VOL(i1, j1, k0);
        float v001 = VOL(i0, j0, k1), v101 = VOL(i1, j0, k1);
        float v011 = VOL(i0, j1, k1), v111 = VOL(i1, j1, k1);
        #undef VOL
        float x00 = v000 + t0 * (v100 - v000);
        float x10 = v010 + t0 * (v110 - v010);
        float x01 = v001 + t0 * (v101 - v001);
        float x11 = v011 + t0 * (v111 - v011);
        float y0 = x00 + t1 * (x10 - x00);
        float y1 = x01 + t1 * (x11 - x01);
        val = y0 + t2 * (y1 - y0);
    }
    out[n] = val;
}

// ---------------- launcher ---------------------------------------------------
extern "C" void kernel_launch(void* const* d_in, const int* in_sizes, int n_in,
                              void* d_out, int out_size) {
    const float* verts = (const float*)d_in[0];
    const void*  faces = (const void*)d_in[1];
    int V = in_sizes[0] / 3;
    int F = in_sizes[1] / 3;
    if (V > MAXV) V = MAXV;
    int Vpad = ((V + VCHUNK - 1) / VCHUNK) * VCHUNK;
    if (Vpad > MAXV) Vpad = MAXV;

    double cr = cbrt((double)out_size);
    int R = (int)(cr + 0.5);

    k_setup<<<1, 256>>>(verts, V, R, (const int*)faces, in_sizes[1] * 2);
    k_faces<<<(F + 255) / 256, 256>>>(verts, faces, F, V);
    k_pack<<<Vpad / 256, 256>>>(verts, V, Vpad);

    dim3 gw((MAXGROUPS4 + TPB - 1) / TPB, Vpad / VCHUNK);
    k_wind<<<gw, TPB>>>();          // launch slot 3 (profiled)

    k_sig<<<(MAXPTS + 255) / 256, 256>>>();
    k_out<<<(out_size + 255) / 256, 256>>>((float*)d_out, R, out_size);
}

// round 14
// speedup vs baseline: 1.0979x; 1.0206x over previous
#include <cuda_runtime.h>
#include <math.h>

// ---------------- static device scratch (no cudaMalloc allowed) -------------
#define MAXV    16384
#define MAXS    66
#define MAXPTS  (66*66*66)
#define TPB     256
#define VCHUNK  128               // verts per block (smem tile) — finer waves
#define MAXGROUPS2 (17*33*65)     // worst case: GPP=17, PR=33, sz=65
#define WEPS    1e-6f

__device__ float  g_vn[MAXV*3];
__device__ float  g_dual[MAXV];
__device__ float4 g_vA[MAXV];     // x,y,z, na.x
__device__ float2 g_vB[MAXV];     // na.y, na.z
__device__ float  g_wsum[MAXPTS];
__device__ float  g_vol[MAXPTS];
__device__ float  g_axes[3][MAXS];
__device__ int    g_dims[4];      // sx, sy, sz, npts
__device__ int    g_b0[3];
__device__ int    g_bsz[3];
__device__ float  g_ratio[3];
__device__ int    g_faces64;      // 1 if faces buffer is int64, 0 if int32

__device__ __forceinline__ float fsqrt_ap(float x) {
    float r; asm("sqrt.approx.f32 %0, %1;" : "=f"(r) : "f"(x)); return r;
}
__device__ __forceinline__ float frcp_ap(float x) {
    float r; asm("rcp.approx.f32 %0, %1;" : "=f"(r) : "f"(x)); return r;
}

// ---------------- K_setup: zero vn/dual + detect dtype + bbox + layout ------
__global__ void k_setup(const float* __restrict__ verts, int V, int R,
                        const int* __restrict__ fdw, int n32) {
    __shared__ float s[6][256];
    int t = threadIdx.x;

    for (int i = t; i < MAXV*3; i += 256) g_vn[i] = 0.0f;
    for (int i = t; i < MAXV;   i += 256) g_dual[i] = 0.0f;

    if (t == 0) {
        int lim = n32 < 4096 ? n32 : 4096;
        int any = 0;
        for (int i = 1; i < lim; i += 2)
            if (fdw[i] != 0) { any = 1; break; }
        g_faces64 = any ? 0 : 1;   // int64 LE small indices -> odd dwords zero
    }

    float mn0 = 1e30f, mn1 = 1e30f, mn2 = 1e30f;
    float mx0 = -1e30f, mx1 = -1e30f, mx2 = -1e30f;
    for (int v = t; v < V; v += 256) {
        float x = verts[3*v+0], y = verts[3*v+1], z = verts[3*v+2];
        mn0 = fminf(mn0, x); mx0 = fmaxf(mx0, x);
        mn1 = fminf(mn1, y); mx1 = fmaxf(mx1, y);
        mn2 = fminf(mn2, z); mx2 = fmaxf(mx2, z);
    }
    s[0][t] = mn0; s[1][t] = mn1; s[2][t] = mn2;
    s[3][t] = mx0; s[4][t] = mx1; s[5][t] = mx2;
    __syncthreads();
    for (int off = 128; off > 0; off >>= 1) {
        if (t < off) {
            s[0][t] = fminf(s[0][t], s[0][t+off]);
            s[1][t] = fminf(s[1][t], s[1][t+off]);
            s[2][t] = fminf(s[2][t], s[2][t+off]);
            s[3][t] = fmaxf(s[3][t], s[3][t+off]);
            s[4][t] = fmaxf(s[4][t], s[4][t+off]);
            s[5][t] = fmaxf(s[5][t], s[5][t+off]);
        }
        __syncthreads();
    }
    if (t == 0) {
        float bmin[3] = { s[0][0], s[1][0], s[2][0] };
        float bmax[3] = { s[3][0], s[4][0], s[5][0] };
        float blen[3], mb = 0.0f;
        for (int i = 0; i < 3; i++) { blen[i] = __fadd_rn(bmax[i], -bmin[i]); mb = fmaxf(mb, blen[i]); }
        float steplen = __fdiv_rn(mb, 64.0f);     // BBOX_DENSITY = 64
        int step[3];
        for (int i = 0; i < 3; i++) {
            int st = (int)__fdiv_rn(blen[i], steplen) + 1;
            if (st < 1) st = 1;
            if (st > 65) st = 65;
            step[i] = st;
        }
        g_dims[0] = step[0]; g_dims[1] = step[1]; g_dims[2] = step[2];
        g_dims[3] = step[0] * step[1] * step[2];
        float Rf = (float)R;
        for (int i = 0; i < 3; i++) {
            int n = step[i];
            double a = (double)bmin[i], b = (double)bmax[i];
            if (n > 1) {
                double stp = (b - a) / (double)(n - 1);
                for (int j = 0; j < n; j++) g_axes[i][j] = (float)((double)j * stp + a);
                g_axes[i][n-1] = (float)b;
            } else {
                g_axes[i][0] = (float)a;
            }
            float lo = floorf(__fmul_rn(__fmul_rn(__fadd_rn(bmin[i], 1.0f), Rf), 0.5f));
            float hi = floorf(__fmul_rn(__fmul_rn(__fadd_rn(bmax[i], 1.0f), Rf), 0.5f));
            int b0 = (int)lo, b1 = (int)hi;
            g_b0[i] = b0;
            int bs = b1 - b0 + 1;
            if (bs < 1) bs = 1;
            g_bsz[i] = bs;
            g_ratio[i] = (float)((double)n / (double)bs);
        }
    }
}

// ---------------- K2: per-face cross + angle-weighted area scatter ----------
__global__ void k_faces(const float* __restrict__ verts,
                        const void* __restrict__ faces_raw, int F, int V) {
    int f = blockIdx.x * blockDim.x + threadIdx.x;
    if (f >= F) return;
    int i0, i1, i2;
    if (g_faces64) {
        const long long* ff = (const long long*)faces_raw;
        i0 = (int)ff[3*f+0]; i1 = (int)ff[3*f+1]; i2 = (int)ff[3*f+2];
    } else {
        const int* fi = (const int*)faces_raw;
        i0 = fi[3*f+0]; i1 = fi[3*f+1]; i2 = fi[3*f+2];
    }
    i0 = min(max(i0, 0), V-1); i1 = min(max(i1, 0), V-1); i2 = min(max(i2, 0), V-1);

    float v0x = verts[3*i0+0], v0y = verts[3*i0+1], v0z = verts[3*i0+2];
    float v1x = verts[3*i1+0], v1y = verts[3*i1+1], v1z = verts[3*i1+2];
    float v2x = verts[3*i2+0], v2y = verts[3*i2+1], v2z = verts[3*i2+2];

    float Ax = v1x - v0x, Ay = v1y - v0y, Az = v1z - v0z;
    float Bx = v2x - v1x, By = v2y - v1y, Bz = v2z - v1z;
    float Cx = v0x - v2x, Cy = v0y - v2y, Cz = v0z - v2z;
    float ex = v2x - v0x, ey = v2y - v0y, ez = v2z - v0z;

    float crx = Ay*ez - Az*ey;
    float cry = Az*ex - Ax*ez;
    float crz = Ax*ey - Ay*ex;
    float area = 0.5f * sqrtf(crx*crx + cry*cry + crz*crz);

    float nA = sqrtf(Ax*Ax + Ay*Ay + Az*Az);
    float nB = sqrtf(Bx*Bx + By*By + Bz*Bz);
    float nC = sqrtf(Cx*Cx + Cy*Cy + Cz*Cz);

    float d_ac = Ax*Cx + Ay*Cy + Az*Cz;
    float d_ab = Ax*Bx + Ay*By + Az*Bz;
    float d_bc = Bx*Cx + By*Cy + Bz*Cz;

    float a0 = acosf(fminf(fmaxf(-d_ac / (1e-10f + nA*nC), -1.0f), 1.0f));
    float a1 = acosf(fminf(fmaxf(-d_ab / (1e-10f + nA*nB), -1.0f), 1.0f));
    float a2 = acosf(fminf(fmaxf(-d_bc / (1e-10f + nB*nC), -1.0f), 1.0f));

    float s0 = sinf(2.0f*a0), s1 = sinf(2.0f*a1), s2 = sinf(2.0f*a2);
    float ssum = s0 + s1 + s2 + 1e-8f;
    float w0 = s0 / ssum, w1 = s1 / ssum, w2 = s2 / ssum;
    float wp0 = 0.5f * (w2 + w1);
    float wp1 = 0.5f * (w0 + w2);
    float wp2 = 0.5f * (w1 + w0);

    atomicAdd(&g_vn[3*i0+0], crx); atomicAdd(&g_vn[3*i0+1], cry); atomicAdd(&g_vn[3*i0+2], crz);
    atomicAdd(&g_vn[3*i1+0], crx); atomicAdd(&g_vn[3*i1+1], cry); atomicAdd(&g_vn[3*i1+2], crz);
    atomicAdd(&g_vn[3*i2+0], crx); atomicAdd(&g_vn[3*i2+1], cry); atomicAdd(&g_vn[3*i2+2], crz);
    atomicAdd(&g_dual[i0], wp0 * area);
    atomicAdd(&g_dual[i1], wp1 * area);
    atomicAdd(&g_dual[i2], wp2 * area);
}

// ---------------- K3: normalize normals, pack; also zero g_wsum --------------
__global__ void k_pack(const float* __restrict__ verts, int V, int Vpad) {
    int v = blockIdx.x * blockDim.x + threadIdx.x;
    int nthr = gridDim.x * blockDim.x;
    for (int i = v; i < MAXPTS; i += nthr) g_wsum[i] = 0.0f;
    if (v >= Vpad) return;
    if (v < V) {
        float nx = g_vn[3*v+0], ny = g_vn[3*v+1], nz = g_vn[3*v+2];
        float len = sqrtf(nx*nx + ny*ny + nz*nz);
        float il = 1.0f / fmaxf(len, 1e-12f);
        float d = g_dual[v];
        float sc = il * d;
        g_vA[v] = make_float4(verts[3*v+0], verts[3*v+1], verts[3*v+2], nx * sc);
        g_vB[v] = make_float2(ny * sc, nz * sc);
    } else {
        g_vA[v] = make_float4(0.f, 0.f, 0.f, 0.f);   // zero normal -> zero term
        g_vB[v] = make_float2(0.f, 0.f);
    }
}

// ---------------- K4: winding-number partial sums ----------------------------
// R11's best-measured core (4x x 2y tile, axis-factorized shared work,
// Montgomery-4 batch reciprocal) with FINER vertex chunks (128) so working
// blocks double and wave-quantization tail drops from ~16% to ~4%.
__global__ void __launch_bounds__(TPB, 3) k_wind() {
    __shared__ float4 sV[VCHUNK];   // x,y,z,nx
    __shared__ float2 sW[VCHUNK];   // ny,nz
    const int sx = g_dims[0], sy = g_dims[1], sz = g_dims[2];
    const int GPP = (sx + 3) >> 2;          // 4-point groups per x-row
    const int PR  = (sy + 1) >> 1;          // y-row pairs
    const int ngroups = GPP * PR * sz;
    const int G0 = blockIdx.x * TPB;
    if (G0 >= ngroups) return;

    {
        int v = threadIdx.x;
        if (v < VCHUNK) {
            int gv = blockIdx.y * VCHUNK + v;
            sV[v] = g_vA[gv];
            sW[v] = g_vB[gv];
        }
    }
    __syncthreads();

    const int G = G0 + threadIdx.x;
    const bool gvalid = (G < ngroups);
    const int Gc = gvalid ? G : 0;
    const int gi = Gc % GPP;
    const int rr = Gc / GPP;
    const int jp = rr % PR;                 // y-pair index
    const int kz = rr / PR;
    const int ix0 = gi * 4;
    const int jy0 = jp * 2;
    const bool has1 = (jy0 + 1 < sy);
    const int jy1 = has1 ? (jy0 + 1) : jy0;
    int nval = sx - ix0; nval = nval > 4 ? 4 : nval;    // 1..4 valid x points
    const float px0 = g_axes[0][ix0];
    const float px1 = g_axes[0][min(ix0+1, sx-1)];
    const float px2 = g_axes[0][min(ix0+2, sx-1)];
    const float px3 = g_axes[0][min(ix0+3, sx-1)];
    const float py0 = g_axes[1][jy0];
    const float py1 = g_axes[1][jy1];
    const float pz  = g_axes[2][kz];
    float aA0=0.f, aA1=0.f, aA2=0.f, aA3=0.f;   // row jy0
    float aB0=0.f, aB1=0.f, aB2=0.f, aB3=0.f;   // row jy1

    #pragma unroll 2
    for (int v = 0; v < VCHUNK; v++) {
        float4 A  = sV[v];
        float2 Bv = sW[v];
        // z-shared (3 ops)
        float dz  = A.z - pz;
        float dzz = dz * dz;
        float tz  = dz * Bv.y;
        // x-shared (4 ops)
        float dx0 = A.x - px0, dx1 = A.x - px1, dx2 = A.x - px2, dx3 = A.x - px3;
        // ---- row A (jy0) ----
        {
            float dy  = A.y - py0;
            float ryz = fmaf(dy, dy, dzz);
            float tyz = fmaf(dy, Bv.x, tz);
            float r20 = fmaf(dx0, dx0, ryz);
            float r21 = fmaf(dx1, dx1, ryz);
            float r22 = fmaf(dx2, dx2, ryz);
            float r23 = fmaf(dx3, dx3, ryz);
            float dt0 = fmaf(dx0, A.w, tyz);
            float dt1 = fmaf(dx1, A.w, tyz);
            float dt2 = fmaf(dx2, A.w, tyz);
            float dt3 = fmaf(dx3, A.w, tyz);
            float dd0 = fmaf(r20, fsqrt_ap(r20), WEPS);
            float dd1 = fmaf(r21, fsqrt_ap(r21), WEPS);
            float dd2 = fmaf(r22, fsqrt_ap(r22), WEPS);
            float dd3 = fmaf(r23, fsqrt_ap(r23), WEPS);
            float p2 = dd0 * dd1;
            float p3 = p2  * dd2;
            float p4 = p3  * dd3;
            float Q  = frcp_ap(p4);
            float Qa = Q  * dd3;
            float Qb = Qa * dd2;
            aA3 = fmaf(dt3, Q  * p3,  aA3);
            aA2 = fmaf(dt2, Qa * p2,  aA2);
            aA1 = fmaf(dt1, Qb * dd0, aA1);
            aA0 = fmaf(dt0, Qb * dd1, aA0);
        }
        // ---- row B (jy1) ----
        {
            float dy  = A.y - py1;
            float ryz = fmaf(dy, dy, dzz);
            float tyz = fmaf(dy, Bv.x, tz);
            float r20 = fmaf(dx0, dx0, ryz);
            float r21 = fmaf(dx1, dx1, ryz);
            float r22 = fmaf(dx2, dx2, ryz);
            float r23 = fmaf(dx3, dx3, ryz);
            float dt0 = fmaf(dx0, A.w, tyz);
            float dt1 = fmaf(dx1, A.w, tyz);
            float dt2 = fmaf(dx2, A.w, tyz);
            float dt3 = fmaf(dx3, A.w, tyz);
            float dd0 = fmaf(r20, fsqrt_ap(r20), WEPS);
            float dd1 = fmaf(r21, fsqrt_ap(r21), WEPS);
            float dd2 = fmaf(r22, fsqrt_ap(r22), WEPS);
            float dd3 = fmaf(r23, fsqrt_ap(r23), WEPS);
            float p2 = dd0 * dd1;
            float p3 = p2  * dd2;
            float p4 = p3  * dd3;
            float Q  = frcp_ap(p4);
            float Qa = Q  * dd3;
            float Qb = Qa * dd2;
            aB3 = fmaf(dt3, Q  * p3,  aB3);
            aB2 = fmaf(dt2, Qa * p2,  aB2);
            aB1 = fmaf(dt1, Qb * dd0, aB1);
            aB0 = fmaf(dt0, Qb * dd1, aB0);
        }
    }

    if (gvalid) {
        int baseA = (kz * sy + jy0) * sx + ix0;
        atomicAdd(&g_wsum[baseA], aA0);
        if (nval > 1) atomicAdd(&g_wsum[baseA+1], aA1);
        if (nval > 2) atomicAdd(&g_wsum[baseA+2], aA2);
        if (nval > 3) atomicAdd(&g_wsum[baseA+3], aA3);
        if (has1) {
            int baseB = baseA + sx;
            atomicAdd(&g_wsum[baseB], aB0);
            if (nval > 1) atomicAdd(&g_wsum[baseB+1], aB1);
            if (nval > 2) atomicAdd(&g_wsum[baseB+2], aB2);
            if (nval > 3) atomicAdd(&g_wsum[baseB+3], aB3);
        }
    }
}

// ---------------- K4b: sigmoid ---------------------------------------------
__global__ void k_sig() {
    int i = blockIdx.x * blockDim.x + threadIdx.x;
    if (i >= g_dims[3]) return;
    float w = g_wsum[i] / 12.566370614359172f;     // / (4*pi)
    float x = (w - 0.5f) * 100.0f;
    g_vol[i] = 1.0f / (1.0f + __expf(-x));
}

// ---------------- K5: trilerp + scatter into R^3, transposed ----------------
__global__ void k_out(float* __restrict__ out, int R, int total) {
    int n = blockIdx.x * blockDim.x + threadIdx.x;
    if (n >= total) return;
    int k = n % R;
    int t = n / R;
    int j = t % R;
    int i = t / R;
    int a = k, b = j, c = i;              // whole axes (x, y, z)
    float val = 0.0f;
    int bi = a - g_b0[0], bj = b - g_b0[1], bk = c - g_b0[2];
    int bsx = g_bsz[0], bsy = g_bsz[1], bsz_ = g_bsz[2];
    if (bi >= 0 && bi < bsx && bj >= 0 && bj < bsy && bk >= 0 && bk < bsz_) {
        int sx = g_dims[0], sy = g_dims[1], sz = g_dims[2];
        float c0 = ((float)bi + 0.5f) * g_ratio[0] - 0.5f;
        float c1 = ((float)bj + 0.5f) * g_ratio[1] - 0.5f;
        float c2 = ((float)bk + 0.5f) * g_ratio[2] - 0.5f;
        c0 = fminf(fmaxf(c0, 0.0f), (float)(sx - 1));
        c1 = fminf(fmaxf(c1, 0.0f), (float)(sy - 1));
        c2 = fminf(fmaxf(c2, 0.0f), (float)(sz - 1));
        int i0 = (int)c0, j0 = (int)c1, k0 = (int)c2;
        float t0 = c0 - (float)i0, t1 = c1 - (float)j0, t2 = c2 - (float)k0;
        int i1 = min(i0 + 1, sx - 1);
        int j1 = min(j0 + 1, sy - 1);
        int k1 = min(k0 + 1, sz - 1);
        #define VOL(I,J,K) g_vol[((K)*sy + (J))*sx + (I)]
        float v000 = VOL(i0, j0, k0), v100 = VOL(i1, j0, k0);
        float v010 = VOL(i0, j1, k0), v110 = VOL(i1, j1, k0);
        float v001 = VOL(i0, j0, k1), v101 = VOL(i1, j0, k1);
        float v011 = VOL(i0, j1, k1), v111 = VOL(i1, j1, k1);
        #undef VOL
        float x00 = v000 + t0 * (v100 - v000);
        float x10 = v010 + t0 * (v110 - v010);
        float x01 = v001 + t0 * (v101 - v001);
        float x11 = v011 + t0 * (v111 - v011);
        float y0 = x00 + t1 * (x10 - x00);
        float y1 = x01 + t1 * (x11 - x01);
        val = y0 + t2 * (y1 - y0);
    }
    out[n] = val;
}

// ---------------- launcher ---------------------------------------------------
extern "C" void kernel_launch(void* const* d_in, const int* in_sizes, int n_in,
                              void* d_out, int out_size) {
    const float* verts = (const float*)d_in[0];
    const void*  faces = (const void*)d_in[1];
    int V = in_sizes[0] / 3;
    int F = in_sizes[1] / 3;
    if (V > MAXV) V = MAXV;
    int Vpad = ((V + VCHUNK - 1) / VCHUNK) * VCHUNK;
    if (Vpad > MAXV) Vpad = MAXV;

    double cr = cbrt((double)out_size);
    int R = (int)(cr + 0.5);

    k_setup<<<1, 256>>>(verts, V, R, (const int*)faces, in_sizes[1] * 2);
    k_faces<<<(F + 255) / 256, 256>>>(verts, faces, F, V);
    k_pack<<<(Vpad + 255) / 256, 256>>>(verts, V, Vpad);

    dim3 gw((MAXGROUPS2 + TPB - 1) / TPB, Vpad / VCHUNK);
    k_wind<<<gw, TPB>>>();          // launch slot 3 (profiled)

    k_sig<<<(MAXPTS + 255) / 256, 256>>>();
    k_out<<<(out_size + 255) / 256, 256>>>((float*)d_out, R, out_size);
}